// round 4
// baseline (speedup 1.0000x reference)
#include <cuda_runtime.h>
#include <cuda_bf16.h>
#include <cstdint>

#define NN 50000
#define EE 600000
#define CC 128

// Scratch (device globals — no runtime allocation allowed)
__device__ float        g_xw[NN * CC];
__device__ float        g_dinv[NN];
__device__ unsigned int g_deg[NN];
__device__ int          g_off[NN + 1];   // CSR row offsets (by dst)
__device__ int          g_cur[NN];       // fill cursors
__device__ int          g_csr[EE];       // src index per in-edge, grouped by dst

// ---------------------------------------------------------------------------
// K0: zero degree counters
// ---------------------------------------------------------------------------
__global__ void k_zero_deg(int n) {
    int i = blockIdx.x * blockDim.x + threadIdx.x;
    if (i < n) g_deg[i] = 0u;
}

// ---------------------------------------------------------------------------
// K1: degree histogram over dst
// ---------------------------------------------------------------------------
__global__ void k_count(const int* __restrict__ ei, int E) {
    int e = blockIdx.x * blockDim.x + threadIdx.x;
    if (e < E) atomicAdd(&g_deg[ei[E + e]], 1u);
}

// ---------------------------------------------------------------------------
// K2: single-block exclusive scan of degrees -> offsets, cursors, dinv
// ---------------------------------------------------------------------------
__global__ __launch_bounds__(1024) void k_scan(int n) {
    const int t = threadIdx.x;
    const int CH = (n + 1023) / 1024;        // elements per thread
    const int lo = t * CH;
    const int hi = min(lo + CH, n);

    // local chunk sum
    unsigned int s = 0;
    for (int i = lo; i < hi; i++) s += g_deg[i];

    // block exclusive scan of 1024 chunk sums
    __shared__ unsigned int warp_tot[32];
    unsigned int v = s;
#pragma unroll
    for (int off = 1; off < 32; off <<= 1) {
        unsigned int u = __shfl_up_sync(0xffffffffu, v, off);
        if ((t & 31) >= off) v += u;
    }
    if ((t & 31) == 31) warp_tot[t >> 5] = v;
    __syncthreads();
    if (t < 32) {
        unsigned int w = warp_tot[t];
        unsigned int vv = w;
#pragma unroll
        for (int off = 1; off < 32; off <<= 1) {
            unsigned int u = __shfl_up_sync(0xffffffffu, vv, off);
            if (t >= off) vv += u;
        }
        warp_tot[t] = vv - w;                // exclusive
    }
    __syncthreads();
    unsigned int base = warp_tot[t >> 5] + (v - s);   // exclusive prefix for this thread

    // write offsets/cursors/dinv for this chunk
    unsigned int run = base;
    for (int i = lo; i < hi; i++) {
        unsigned int d = g_deg[i];
        g_off[i] = (int)run;
        g_cur[i] = (int)run;
        g_dinv[i] = rsqrtf((float)d + 1.0f);
        run += d;
    }
    if (t == 1023) g_off[n] = (int)run;      // == E
}

// ---------------------------------------------------------------------------
// K3: CSR fill — bucket each edge's src under its dst
// ---------------------------------------------------------------------------
__global__ void k_fill(const int* __restrict__ ei, int E) {
    int e = blockIdx.x * blockDim.x + threadIdx.x;
    if (e >= E) return;
    int src = ei[e];
    int dst = ei[E + e];
    int pos = atomicAdd(&g_cur[dst], 1);
    g_csr[pos] = src;
}

// ---------------------------------------------------------------------------
// K4: xw = x @ W   (fp32, 64-row x 128-col tile per block, k-chunked smem)
// ---------------------------------------------------------------------------
__global__ __launch_bounds__(256) void k_gemm(const float* __restrict__ x,
                                              const float* __restrict__ W,
                                              int n) {
    __shared__ float xs[32 * 68];
    __shared__ float ws[32 * 128];

    const int row0 = blockIdx.x * 64;
    const int t  = threadIdx.x;
    const int tc = t & 15;
    const int tr = t >> 4;

    float acc[4][8];
#pragma unroll
    for (int i = 0; i < 4; i++)
#pragma unroll
        for (int j = 0; j < 8; j++) acc[i][j] = 0.0f;

    for (int kc = 0; kc < 128; kc += 32) {
        __syncthreads();
#pragma unroll
        for (int j = t; j < 512; j += 256) {
            int r  = j >> 3;
            int k4 = j & 7;
            int row = row0 + r;
            if (row >= n) row = n - 1;
            float4 v = ((const float4*)x)[row * 32 + (kc >> 2) + k4];
            xs[(k4 * 4 + 0) * 68 + r] = v.x;
            xs[(k4 * 4 + 1) * 68 + r] = v.y;
            xs[(k4 * 4 + 2) * 68 + r] = v.z;
            xs[(k4 * 4 + 3) * 68 + r] = v.w;
        }
#pragma unroll
        for (int j = t; j < 1024; j += 256) {
            ((float4*)ws)[j] = ((const float4*)W)[kc * 32 + j];
        }
        __syncthreads();

#pragma unroll
        for (int k = 0; k < 32; k++) {
            float4 xv = *(const float4*)&xs[k * 68 + tr * 4];
            float4 w0 = *(const float4*)&ws[k * 128 + tc * 8];
            float4 w1 = *(const float4*)&ws[k * 128 + tc * 8 + 4];
            float xr[4] = {xv.x, xv.y, xv.z, xv.w};
            float wv[8] = {w0.x, w0.y, w0.z, w0.w, w1.x, w1.y, w1.z, w1.w};
#pragma unroll
            for (int i = 0; i < 4; i++)
#pragma unroll
                for (int j = 0; j < 8; j++)
                    acc[i][j] = fmaf(xr[i], wv[j], acc[i][j]);
        }
    }

#pragma unroll
    for (int i = 0; i < 4; i++) {
        int row = row0 + tr * 4 + i;
        if (row < n) {
            float4 o0 = make_float4(acc[i][0], acc[i][1], acc[i][2], acc[i][3]);
            float4 o1 = make_float4(acc[i][4], acc[i][5], acc[i][6], acc[i][7]);
            ((float4*)g_xw)[row * 32 + tc * 2]     = o0;
            ((float4*)g_xw)[row * 32 + tc * 2 + 1] = o1;
        }
    }
}

// ---------------------------------------------------------------------------
// K5: fused gather + self-loop + bias + LayerNorm + LeakyReLU + residual.
//     One warp per node; register accumulator; no atomics anywhere.
// ---------------------------------------------------------------------------
__global__ __launch_bounds__(256) void k_gather(const float* __restrict__ x,
                                                const float* __restrict__ b,
                                                const float* __restrict__ gamma,
                                                const float* __restrict__ beta,
                                                float* __restrict__ out, int n) {
    int gt   = blockIdx.x * blockDim.x + threadIdx.x;
    int node = gt >> 5;
    int lane = gt & 31;
    if (node >= n) return;

    const float dinv_n = g_dinv[node];
    const int off0 = g_off[node];
    const int off1 = g_off[node + 1];

    // self-loop term: xw[node] * dinv^2
    float4 v0 = ((const float4*)g_xw)[node * 32 + lane];
    float sl = dinv_n * dinv_n;
    float ax = v0.x * sl, ay = v0.y * sl, az = v0.z * sl, aw = v0.w * sl;

    // in-edge gather, 4-wide software pipelining for MLP
    int i = off0;
    for (; i + 4 <= off1; i += 4) {
        int s0 = g_csr[i], s1 = g_csr[i + 1], s2 = g_csr[i + 2], s3 = g_csr[i + 3];
        float n0 = dinv_n * g_dinv[s0];
        float n1 = dinv_n * g_dinv[s1];
        float n2 = dinv_n * g_dinv[s2];
        float n3 = dinv_n * g_dinv[s3];
        float4 w0 = ((const float4*)g_xw)[s0 * 32 + lane];
        float4 w1 = ((const float4*)g_xw)[s1 * 32 + lane];
        float4 w2 = ((const float4*)g_xw)[s2 * 32 + lane];
        float4 w3 = ((const float4*)g_xw)[s3 * 32 + lane];
        ax = fmaf(n0, w0.x, ax); ay = fmaf(n0, w0.y, ay);
        az = fmaf(n0, w0.z, az); aw = fmaf(n0, w0.w, aw);
        ax = fmaf(n1, w1.x, ax); ay = fmaf(n1, w1.y, ay);
        az = fmaf(n1, w1.z, az); aw = fmaf(n1, w1.w, aw);
        ax = fmaf(n2, w2.x, ax); ay = fmaf(n2, w2.y, ay);
        az = fmaf(n2, w2.z, az); aw = fmaf(n2, w2.w, aw);
        ax = fmaf(n3, w3.x, ax); ay = fmaf(n3, w3.y, ay);
        az = fmaf(n3, w3.z, az); aw = fmaf(n3, w3.w, aw);
    }
    for (; i < off1; i++) {
        int s = g_csr[i];
        float nm = dinv_n * g_dinv[s];
        float4 w = ((const float4*)g_xw)[s * 32 + lane];
        ax = fmaf(nm, w.x, ax); ay = fmaf(nm, w.y, ay);
        az = fmaf(nm, w.z, az); aw = fmaf(nm, w.w, aw);
    }

    // + bias
    float4 bv = ((const float4*)b)[lane];
    ax += bv.x; ay += bv.y; az += bv.z; aw += bv.w;

    // LayerNorm over 128 channels (warp reduction, 4 per lane)
    float sum = ax + ay + az + aw;
#pragma unroll
    for (int off = 16; off > 0; off >>= 1)
        sum += __shfl_xor_sync(0xffffffffu, sum, off);
    float mean = sum * (1.0f / 128.0f);

    float cx = ax - mean, cy = ay - mean, cz = az - mean, cw = aw - mean;
    float sq = cx * cx + cy * cy + cz * cz + cw * cw;
#pragma unroll
    for (int off = 16; off > 0; off >>= 1)
        sq += __shfl_xor_sync(0xffffffffu, sq, off);
    float var  = sq * (1.0f / 128.0f);
    float rstd = rsqrtf(var + 1e-5f);

    float4 g  = ((const float4*)gamma)[lane];
    float4 be = ((const float4*)beta)[lane];
    float4 xr = ((const float4*)x)[node * 32 + lane];

    float4 o;
    o.x = fmaf(cx * rstd, g.x, be.x);
    o.y = fmaf(cy * rstd, g.y, be.y);
    o.z = fmaf(cz * rstd, g.z, be.z);
    o.w = fmaf(cw * rstd, g.w, be.w);
    o.x = (o.x >= 0.0f ? o.x : 0.01f * o.x) + xr.x;
    o.y = (o.y >= 0.0f ? o.y : 0.01f * o.y) + xr.y;
    o.z = (o.z >= 0.0f ? o.z : 0.01f * o.z) + xr.z;
    o.w = (o.w >= 0.0f ? o.w : 0.01f * o.w) + xr.w;

    ((float4*)out)[node * 32 + lane] = o;
}

// ---------------------------------------------------------------------------
// Host launcher (graph-capturable: kernel launches only, default stream)
// ---------------------------------------------------------------------------
extern "C" void kernel_launch(void* const* d_in, const int* in_sizes, int n_in,
                              void* d_out, int out_size) {
    const float* x     = (const float*)d_in[0];
    const int*   ei    = (const int*)d_in[1];
    const float* W     = (const float*)d_in[2];
    const float* b     = (const float*)d_in[3];
    const float* gamma = (const float*)d_in[4];
    const float* beta  = (const float*)d_in[5];
    float* out = (float*)d_out;

    const int n = in_sizes[0] / CC;      // 50000
    const int E = in_sizes[1] / 2;       // 600000

    k_zero_deg<<<(n + 255) / 256, 256>>>(n);
    k_count<<<(E + 255) / 256, 256>>>(ei, E);
    k_scan<<<1, 1024>>>(n);
    k_fill<<<(E + 255) / 256, 256>>>(ei, E);
    k_gemm<<<(n + 63) / 64, 256>>>(x, W, n);
    k_gather<<<(n * 32 + 255) / 256, 256>>>(x, b, gamma, beta, out, n);
}

// round 11
// speedup vs baseline: 1.0886x; 1.0886x over previous
#include <cuda_runtime.h>
#include <cuda_bf16.h>
#include <cstdint>

#define NN 50000
#define EE 600000
#define CC 128

// Scratch (device globals — no runtime allocation allowed)
__device__ float        g_xw[NN * CC];
__device__ float        g_dinv[NN];
__device__ unsigned int g_deg[NN];
__device__ int          g_off[NN + 1];   // CSR row offsets (by dst)
__device__ int          g_rank[EE];      // per-edge rank within its dst bucket
__device__ int          g_csr[EE];       // src index per in-edge, grouped by dst
__device__ float        g_nrm[EE];       // dinv[src]*dinv[dst], same layout as g_csr

// ---------------------------------------------------------------------------
// K0: zero degree counters
// ---------------------------------------------------------------------------
__global__ void k_zero_deg(int n) {
    int i = blockIdx.x * blockDim.x + threadIdx.x;
    if (i < n) g_deg[i] = 0u;
}

// ---------------------------------------------------------------------------
// K1: degree histogram over dst + per-edge rank (reuses the same atomic)
// ---------------------------------------------------------------------------
__global__ void k_count(const int* __restrict__ ei, int E) {
    int e = blockIdx.x * blockDim.x + threadIdx.x;
    if (e < E) g_rank[e] = (int)atomicAdd(&g_deg[ei[E + e]], 1u);
}

// ---------------------------------------------------------------------------
// K2: single-block exclusive scan of degrees -> offsets + dinv
// ---------------------------------------------------------------------------
__global__ __launch_bounds__(1024) void k_scan(int n) {
    const int t = threadIdx.x;
    const int CH = (n + 1023) / 1024;
    const int lo = t * CH;
    const int hi = min(lo + CH, n);

    unsigned int s = 0;
    for (int i = lo; i < hi; i++) s += g_deg[i];

    __shared__ unsigned int warp_tot[32];
    unsigned int v = s;
#pragma unroll
    for (int off = 1; off < 32; off <<= 1) {
        unsigned int u = __shfl_up_sync(0xffffffffu, v, off);
        if ((t & 31) >= off) v += u;
    }
    if ((t & 31) == 31) warp_tot[t >> 5] = v;
    __syncthreads();
    if (t < 32) {
        unsigned int w = warp_tot[t];
        unsigned int vv = w;
#pragma unroll
        for (int off = 1; off < 32; off <<= 1) {
            unsigned int u = __shfl_up_sync(0xffffffffu, vv, off);
            if (t >= off) vv += u;
        }
        warp_tot[t] = vv - w;
    }
    __syncthreads();
    unsigned int base = warp_tot[t >> 5] + (v - s);

    unsigned int run = base;
    for (int i = lo; i < hi; i++) {
        unsigned int d = g_deg[i];
        g_off[i]  = (int)run;
        g_dinv[i] = rsqrtf((float)d + 1.0f);
        run += d;
    }
    if (t == 1023) g_off[n] = (int)run;
}

// ---------------------------------------------------------------------------
// K3: CSR fill — atomic-free (pos = off[dst] + rank[e]); also precompute norm
// ---------------------------------------------------------------------------
__global__ void k_fill(const int* __restrict__ ei, int E) {
    int e = blockIdx.x * blockDim.x + threadIdx.x;
    if (e >= E) return;
    int src = ei[e];
    int dst = ei[E + e];
    int pos = g_off[dst] + g_rank[e];
    g_csr[pos] = src;
    g_nrm[pos] = g_dinv[src] * g_dinv[dst];
}

// ---------------------------------------------------------------------------
// K4: xw = x @ W   (fp32, 64-row x 128-col tile per block, k-chunked smem)
// ---------------------------------------------------------------------------
__global__ __launch_bounds__(256) void k_gemm(const float* __restrict__ x,
                                              const float* __restrict__ W,
                                              int n) {
    __shared__ float xs[32 * 68];
    __shared__ float ws[32 * 128];

    const int row0 = blockIdx.x * 64;
    const int t  = threadIdx.x;
    const int tc = t & 15;
    const int tr = t >> 4;

    float acc[4][8];
#pragma unroll
    for (int i = 0; i < 4; i++)
#pragma unroll
        for (int j = 0; j < 8; j++) acc[i][j] = 0.0f;

    for (int kc = 0; kc < 128; kc += 32) {
        __syncthreads();
#pragma unroll
        for (int j = t; j < 512; j += 256) {
            int r  = j >> 3;
            int k4 = j & 7;
            int row = row0 + r;
            if (row >= n) row = n - 1;
            float4 v = ((const float4*)x)[row * 32 + (kc >> 2) + k4];
            xs[(k4 * 4 + 0) * 68 + r] = v.x;
            xs[(k4 * 4 + 1) * 68 + r] = v.y;
            xs[(k4 * 4 + 2) * 68 + r] = v.z;
            xs[(k4 * 4 + 3) * 68 + r] = v.w;
        }
#pragma unroll
        for (int j = t; j < 1024; j += 256) {
            ((float4*)ws)[j] = ((const float4*)W)[kc * 32 + j];
        }
        __syncthreads();

#pragma unroll
        for (int k = 0; k < 32; k++) {
            float4 xv = *(const float4*)&xs[k * 68 + tr * 4];
            float4 w0 = *(const float4*)&ws[k * 128 + tc * 8];
            float4 w1 = *(const float4*)&ws[k * 128 + tc * 8 + 4];
            float xr[4] = {xv.x, xv.y, xv.z, xv.w};
            float wv[8] = {w0.x, w0.y, w0.z, w0.w, w1.x, w1.y, w1.z, w1.w};
#pragma unroll
            for (int i = 0; i < 4; i++)
#pragma unroll
                for (int j = 0; j < 8; j++)
                    acc[i][j] = fmaf(xr[i], wv[j], acc[i][j]);
        }
    }

#pragma unroll
    for (int i = 0; i < 4; i++) {
        int row = row0 + tr * 4 + i;
        if (row < n) {
            float4 o0 = make_float4(acc[i][0], acc[i][1], acc[i][2], acc[i][3]);
            float4 o1 = make_float4(acc[i][4], acc[i][5], acc[i][6], acc[i][7]);
            ((float4*)g_xw)[row * 32 + tc * 2]     = o0;
            ((float4*)g_xw)[row * 32 + tc * 2 + 1] = o1;
        }
    }
}

// ---------------------------------------------------------------------------
// K5: fused gather + self-loop + bias + LayerNorm + LeakyReLU + residual.
//     One warp per node. Lane-parallel (src,nrm) fetch, shfl broadcast, then
//     only INDEPENDENT float4 gathers in the hot loop (MLP via unroll-4).
// ---------------------------------------------------------------------------
__global__ __launch_bounds__(256) void k_gather(const float* __restrict__ x,
                                                const float* __restrict__ b,
                                                const float* __restrict__ gamma,
                                                const float* __restrict__ beta,
                                                float* __restrict__ out, int n) {
    int gt   = blockIdx.x * blockDim.x + threadIdx.x;
    int node = gt >> 5;
    int lane = gt & 31;
    if (node >= n) return;

    const float dinv_n = g_dinv[node];
    const int off0 = g_off[node];
    const int deg  = g_off[node + 1] - off0;

    // self-loop term: xw[node] * dinv^2
    float4 v0 = ((const float4*)g_xw)[node * 32 + lane];
    float sl = dinv_n * dinv_n;
    float ax = v0.x * sl, ay = v0.y * sl, az = v0.z * sl, aw = v0.w * sl;

    for (int base = 0; base < deg; base += 32) {
        int cnt = min(32, deg - base);
        int   sreg = 0;
        float nreg = 0.0f;
        if (lane < cnt) {                         // coalesced fetch of edge metadata
            sreg = g_csr[off0 + base + lane];
            nreg = g_nrm[off0 + base + lane];
        }
        int j = 0;
        for (; j + 4 <= cnt; j += 4) {
            int   s0 = __shfl_sync(0xffffffffu, sreg, j);
            int   s1 = __shfl_sync(0xffffffffu, sreg, j + 1);
            int   s2 = __shfl_sync(0xffffffffu, sreg, j + 2);
            int   s3 = __shfl_sync(0xffffffffu, sreg, j + 3);
            float n0 = __shfl_sync(0xffffffffu, nreg, j);
            float n1 = __shfl_sync(0xffffffffu, nreg, j + 1);
            float n2 = __shfl_sync(0xffffffffu, nreg, j + 2);
            float n3 = __shfl_sync(0xffffffffu, nreg, j + 3);
            float4 w0 = ((const float4*)g_xw)[s0 * 32 + lane];
            float4 w1 = ((const float4*)g_xw)[s1 * 32 + lane];
            float4 w2 = ((const float4*)g_xw)[s2 * 32 + lane];
            float4 w3 = ((const float4*)g_xw)[s3 * 32 + lane];
            ax = fmaf(n0, w0.x, ax); ay = fmaf(n0, w0.y, ay);
            az = fmaf(n0, w0.z, az); aw = fmaf(n0, w0.w, aw);
            ax = fmaf(n1, w1.x, ax); ay = fmaf(n1, w1.y, ay);
            az = fmaf(n1, w1.z, az); aw = fmaf(n1, w1.w, aw);
            ax = fmaf(n2, w2.x, ax); ay = fmaf(n2, w2.y, ay);
            az = fmaf(n2, w2.z, az); aw = fmaf(n2, w2.w, aw);
            ax = fmaf(n3, w3.x, ax); ay = fmaf(n3, w3.y, ay);
            az = fmaf(n3, w3.z, az); aw = fmaf(n3, w3.w, aw);
        }
        if (j + 2 <= cnt) {
            int   s0 = __shfl_sync(0xffffffffu, sreg, j);
            int   s1 = __shfl_sync(0xffffffffu, sreg, j + 1);
            float n0 = __shfl_sync(0xffffffffu, nreg, j);
            float n1 = __shfl_sync(0xffffffffu, nreg, j + 1);
            float4 w0 = ((const float4*)g_xw)[s0 * 32 + lane];
            float4 w1 = ((const float4*)g_xw)[s1 * 32 + lane];
            ax = fmaf(n0, w0.x, ax); ay = fmaf(n0, w0.y, ay);
            az = fmaf(n0, w0.z, az); aw = fmaf(n0, w0.w, aw);
            ax = fmaf(n1, w1.x, ax); ay = fmaf(n1, w1.y, ay);
            az = fmaf(n1, w1.z, az); aw = fmaf(n1, w1.w, aw);
            j += 2;
        }
        if (j < cnt) {
            int   s0 = __shfl_sync(0xffffffffu, sreg, j);
            float n0 = __shfl_sync(0xffffffffu, nreg, j);
            float4 w = ((const float4*)g_xw)[s0 * 32 + lane];
            ax = fmaf(n0, w.x, ax); ay = fmaf(n0, w.y, ay);
            az = fmaf(n0, w.z, az); aw = fmaf(n0, w.w, aw);
        }
    }

    // + bias
    float4 bv = ((const float4*)b)[lane];
    ax += bv.x; ay += bv.y; az += bv.z; aw += bv.w;

    // LayerNorm over 128 channels
    float sum = ax + ay + az + aw;
#pragma unroll
    for (int off = 16; off > 0; off >>= 1)
        sum += __shfl_xor_sync(0xffffffffu, sum, off);
    float mean = sum * (1.0f / 128.0f);

    float cx = ax - mean, cy = ay - mean, cz = az - mean, cw = aw - mean;
    float sq = cx * cx + cy * cy + cz * cz + cw * cw;
#pragma unroll
    for (int off = 16; off > 0; off >>= 1)
        sq += __shfl_xor_sync(0xffffffffu, sq, off);
    float var  = sq * (1.0f / 128.0f);
    float rstd = rsqrtf(var + 1e-5f);

    float4 g  = ((const float4*)gamma)[lane];
    float4 be = ((const float4*)beta)[lane];
    float4 xr = ((const float4*)x)[node * 32 + lane];

    float4 o;
    o.x = fmaf(cx * rstd, g.x, be.x);
    o.y = fmaf(cy * rstd, g.y, be.y);
    o.z = fmaf(cz * rstd, g.z, be.z);
    o.w = fmaf(cw * rstd, g.w, be.w);
    o.x = (o.x >= 0.0f ? o.x : 0.01f * o.x) + xr.x;
    o.y = (o.y >= 0.0f ? o.y : 0.01f * o.y) + xr.y;
    o.z = (o.z >= 0.0f ? o.z : 0.01f * o.z) + xr.z;
    o.w = (o.w >= 0.0f ? o.w : 0.01f * o.w) + xr.w;

    ((float4*)out)[node * 32 + lane] = o;
}

// ---------------------------------------------------------------------------
// Host launcher (graph-capturable: kernel launches only, default stream)
// ---------------------------------------------------------------------------
extern "C" void kernel_launch(void* const* d_in, const int* in_sizes, int n_in,
                              void* d_out, int out_size) {
    const float* x     = (const float*)d_in[0];
    const int*   ei    = (const int*)d_in[1];
    const float* W     = (const float*)d_in[2];
    const float* b     = (const float*)d_in[3];
    const float* gamma = (const float*)d_in[4];
    const float* beta  = (const float*)d_in[5];
    float* out = (float*)d_out;

    const int n = in_sizes[0] / CC;      // 50000
    const int E = in_sizes[1] / 2;       // 600000

    k_zero_deg<<<(n + 255) / 256, 256>>>(n);
    k_count<<<(E + 255) / 256, 256>>>(ei, E);
    k_scan<<<1, 1024>>>(n);
    k_fill<<<(E + 255) / 256, 256>>>(ei, E);
    k_gemm<<<(n + 63) / 64, 256>>>(x, W, n);
    k_gather<<<(n * 32 + 255) / 256, 256>>>(x, b, gamma, beta, out, n);
}

// round 12
// speedup vs baseline: 1.3247x; 1.2168x over previous
#include <cuda_runtime.h>
#include <cuda_bf16.h>
#include <cstdint>

#define NN 50000
#define EE 600000
#define CC 128

// Scratch (device globals — no runtime allocation allowed)
__device__ float        g_xw[NN * CC];
__device__ float        g_agg[NN * CC];
__device__ float        g_dinv[NN];
__device__ unsigned int g_deg[NN];

// ---------------------------------------------------------------------------
// K0: zero degree counters
// ---------------------------------------------------------------------------
__global__ void k_zero_deg(int n) {
    int i = blockIdx.x * blockDim.x + threadIdx.x;
    if (i < n) g_deg[i] = 0u;
}

// ---------------------------------------------------------------------------
// K1: degree histogram over dst
// ---------------------------------------------------------------------------
__global__ void k_count(const int* __restrict__ ei, int E) {
    int e = blockIdx.x * blockDim.x + threadIdx.x;
    if (e < E) atomicAdd(&g_deg[ei[E + e]], 1u);
}

// ---------------------------------------------------------------------------
// K1b: dinv = rsqrt(deg + 1)
// ---------------------------------------------------------------------------
__global__ void k_dinv(int n) {
    int i = blockIdx.x * blockDim.x + threadIdx.x;
    if (i < n) g_dinv[i] = rsqrtf((float)g_deg[i] + 1.0f);
}

// ---------------------------------------------------------------------------
// K2: xw = x @ W  (fp32, 64x128 tile) — epilogue also writes
//     g_agg = xw * dinv^2  (self-loop init), killing the old k_node_init.
// ---------------------------------------------------------------------------
__global__ __launch_bounds__(256) void k_gemm(const float* __restrict__ x,
                                              const float* __restrict__ W,
                                              int n) {
    __shared__ float xs[32 * 68];    // [k][row]
    __shared__ float ws[32 * 128];   // [k][col]

    const int row0 = blockIdx.x * 64;
    const int t  = threadIdx.x;
    const int tc = t & 15;           // cols [tc*8, tc*8+8)
    const int tr = t >> 4;           // rows [tr*4, tr*4+4)

    float acc[4][8];
#pragma unroll
    for (int i = 0; i < 4; i++)
#pragma unroll
        for (int j = 0; j < 8; j++) acc[i][j] = 0.0f;

    for (int kc = 0; kc < 128; kc += 32) {
        __syncthreads();
#pragma unroll
        for (int j = t; j < 512; j += 256) {
            int r  = j >> 3;
            int k4 = j & 7;
            int row = row0 + r;
            if (row >= n) row = n - 1;
            float4 v = ((const float4*)x)[row * 32 + (kc >> 2) + k4];
            xs[(k4 * 4 + 0) * 68 + r] = v.x;
            xs[(k4 * 4 + 1) * 68 + r] = v.y;
            xs[(k4 * 4 + 2) * 68 + r] = v.z;
            xs[(k4 * 4 + 3) * 68 + r] = v.w;
        }
#pragma unroll
        for (int j = t; j < 1024; j += 256) {
            ((float4*)ws)[j] = ((const float4*)W)[kc * 32 + j];
        }
        __syncthreads();

#pragma unroll
        for (int k = 0; k < 32; k++) {
            float4 xv = *(const float4*)&xs[k * 68 + tr * 4];
            float4 w0 = *(const float4*)&ws[k * 128 + tc * 8];
            float4 w1 = *(const float4*)&ws[k * 128 + tc * 8 + 4];
            float xr[4] = {xv.x, xv.y, xv.z, xv.w};
            float wv[8] = {w0.x, w0.y, w0.z, w0.w, w1.x, w1.y, w1.z, w1.w};
#pragma unroll
            for (int i = 0; i < 4; i++)
#pragma unroll
                for (int j = 0; j < 8; j++)
                    acc[i][j] = fmaf(xr[i], wv[j], acc[i][j]);
        }
    }

#pragma unroll
    for (int i = 0; i < 4; i++) {
        int row = row0 + tr * 4 + i;
        if (row < n) {
            float4 o0 = make_float4(acc[i][0], acc[i][1], acc[i][2], acc[i][3]);
            float4 o1 = make_float4(acc[i][4], acc[i][5], acc[i][6], acc[i][7]);
            ((float4*)g_xw)[row * 32 + tc * 2]     = o0;
            ((float4*)g_xw)[row * 32 + tc * 2 + 1] = o1;
            float dv = g_dinv[row];
            float s  = dv * dv;
            float4 a0 = make_float4(o0.x * s, o0.y * s, o0.z * s, o0.w * s);
            float4 a1 = make_float4(o1.x * s, o1.y * s, o1.z * s, o1.w * s);
            ((float4*)g_agg)[row * 32 + tc * 2]     = a0;
            ((float4*)g_agg)[row * 32 + tc * 2 + 1] = a1;
        }
    }
}

// ---------------------------------------------------------------------------
// K3: edge scatter — one warp per edge, vector RED into agg[dst]
// ---------------------------------------------------------------------------
__global__ void k_scatter(const int* __restrict__ ei, int E) {
    int gt   = blockIdx.x * blockDim.x + threadIdx.x;
    int e    = gt >> 5;
    int lane = gt & 31;
    if (e >= E) return;
    int src = __ldg(&ei[e]);
    int dst = __ldg(&ei[E + e]);
    float norm = g_dinv[src] * g_dinv[dst];
    float4 v = ((const float4*)g_xw)[src * 32 + lane];
    v.x *= norm; v.y *= norm; v.z *= norm; v.w *= norm;
    float* p = g_agg + (size_t)dst * CC + lane * 4;
    asm volatile("red.global.add.v4.f32 [%0], {%1, %2, %3, %4};"
                 :: "l"(p), "f"(v.x), "f"(v.y), "f"(v.z), "f"(v.w)
                 : "memory");
}

// ---------------------------------------------------------------------------
// K4: finalize — bias, LayerNorm(C=128), LeakyReLU, residual. One warp/node.
// ---------------------------------------------------------------------------
__global__ void k_finalize(const float* __restrict__ x,
                           const float* __restrict__ b,
                           const float* __restrict__ gamma,
                           const float* __restrict__ beta,
                           float* __restrict__ out, int n) {
    int gt   = blockIdx.x * blockDim.x + threadIdx.x;
    int node = gt >> 5;
    int lane = gt & 31;
    if (node >= n) return;

    float4 v  = ((const float4*)g_agg)[node * 32 + lane];
    float4 bv = ((const float4*)b)[lane];
    v.x += bv.x; v.y += bv.y; v.z += bv.z; v.w += bv.w;

    float sum = v.x + v.y + v.z + v.w;
#pragma unroll
    for (int off = 16; off > 0; off >>= 1)
        sum += __shfl_xor_sync(0xffffffffu, sum, off);
    float mean = sum * (1.0f / 128.0f);

    float cx = v.x - mean, cy = v.y - mean, cz = v.z - mean, cw = v.w - mean;
    float sq = cx * cx + cy * cy + cz * cz + cw * cw;
#pragma unroll
    for (int off = 16; off > 0; off >>= 1)
        sq += __shfl_xor_sync(0xffffffffu, sq, off);
    float var  = sq * (1.0f / 128.0f);
    float rstd = rsqrtf(var + 1e-5f);

    float4 g  = ((const float4*)gamma)[lane];
    float4 be = ((const float4*)beta)[lane];
    float4 xr = ((const float4*)x)[node * 32 + lane];

    float4 o;
    o.x = fmaf(cx * rstd, g.x, be.x);
    o.y = fmaf(cy * rstd, g.y, be.y);
    o.z = fmaf(cz * rstd, g.z, be.z);
    o.w = fmaf(cw * rstd, g.w, be.w);
    o.x = (o.x >= 0.0f ? o.x : 0.01f * o.x) + xr.x;
    o.y = (o.y >= 0.0f ? o.y : 0.01f * o.y) + xr.y;
    o.z = (o.z >= 0.0f ? o.z : 0.01f * o.z) + xr.z;
    o.w = (o.w >= 0.0f ? o.w : 0.01f * o.w) + xr.w;

    ((float4*)out)[node * 32 + lane] = o;
}

// ---------------------------------------------------------------------------
// Host launcher (graph-capturable: kernel launches only, default stream)
// ---------------------------------------------------------------------------
extern "C" void kernel_launch(void* const* d_in, const int* in_sizes, int n_in,
                              void* d_out, int out_size) {
    const float* x     = (const float*)d_in[0];
    const int*   ei    = (const int*)d_in[1];
    const float* W     = (const float*)d_in[2];
    const float* b     = (const float*)d_in[3];
    const float* gamma = (const float*)d_in[4];
    const float* beta  = (const float*)d_in[5];
    float* out = (float*)d_out;

    const int n = in_sizes[0] / CC;      // 50000
    const int E = in_sizes[1] / 2;       // 600000

    k_zero_deg<<<(n + 255) / 256, 256>>>(n);
    k_count<<<(E + 255) / 256, 256>>>(ei, E);
    k_dinv<<<(n + 255) / 256, 256>>>(n);
    k_gemm<<<(n + 63) / 64, 256>>>(x, W, n);
    k_scatter<<<((long long)E * 32 + 255) / 256, 256>>>(ei, E);
    k_finalize<<<(n * 32 + 255) / 256, 256>>>(x, b, gamma, beta, out, n);
}

// round 14
// speedup vs baseline: 1.8560x; 1.4011x over previous
#include <cuda_runtime.h>
#include <cuda_bf16.h>
#include <cstdint>

#define NN 50000
#define EE 600000
#define CC 128

// Scratch (device globals — no runtime allocation allowed)
__device__ float        g_xw[NN * CC];
__device__ float        g_agg[NN * CC];
__device__ float        g_dinv[NN];
__device__ unsigned int g_deg[NN];

// ---------------------------------------------------------------------------
// K0: zero degree counters
// ---------------------------------------------------------------------------
__global__ void k_zero_deg(int n) {
    int i = blockIdx.x * blockDim.x + threadIdx.x;
    if (i < n) g_deg[i] = 0u;
}

// ---------------------------------------------------------------------------
// K1: degree histogram over dst
// ---------------------------------------------------------------------------
__global__ void k_count(const int* __restrict__ ei, int E) {
    int e = blockIdx.x * blockDim.x + threadIdx.x;
    if (e < E) atomicAdd(&g_deg[ei[E + e]], 1u);
}

// ---------------------------------------------------------------------------
// K1b: dinv = rsqrt(deg + 1)
// ---------------------------------------------------------------------------
__global__ void k_dinv(int n) {
    int i = blockIdx.x * blockDim.x + threadIdx.x;
    if (i < n) g_dinv[i] = rsqrtf((float)g_deg[i] + 1.0f);
}

// ---------------------------------------------------------------------------
// K2: xw = x @ W via tf32 tensor cores (mma.sync.m16n8k8).
//     Block tile 128x128, 8 warps in 4(m) x 2(n). K chunked by 32 via smem.
//     Epilogue writes g_xw and g_agg = xw * dinv^2 (self-loop init).
//
//     Smem strides chosen for conflict-free fragment access:
//       xs[m][k]  stride 36  -> a-frag bank = (4g + c)  : all 32 distinct
//       ws[k][n]  stride 136 -> b-frag bank = (8c + g)  : all 32 distinct
// ---------------------------------------------------------------------------
__device__ __forceinline__ uint32_t f2tf32(float f) {
    uint32_t u;
    asm("cvt.rna.tf32.f32 %0, %1;" : "=r"(u) : "f"(f));
    return u;
}

__global__ __launch_bounds__(256) void k_gemm_tc(const float* __restrict__ x,
                                                 const float* __restrict__ W,
                                                 int n) {
    __shared__ uint32_t xs[128 * 36];   // [m][k] tf32 bits, k-stride 36
    __shared__ uint32_t ws[32 * 136];   // [k][n] tf32 bits, n-stride 136

    const int t      = threadIdx.x;
    const int lane   = t & 31;
    const int warp   = t >> 5;
    const int g      = lane >> 2;       // groupID 0..7
    const int c      = lane & 3;        // thread-in-group 0..3
    const int warp_m = warp >> 1;       // 0..3  (32 rows each)
    const int warp_n = warp & 1;        // 0..1  (64 cols each)
    const int row0   = blockIdx.x * 128;

    float acc[2][8][4];
#pragma unroll
    for (int mt = 0; mt < 2; mt++)
#pragma unroll
        for (int nt = 0; nt < 8; nt++)
#pragma unroll
            for (int q = 0; q < 4; q++) acc[mt][nt][q] = 0.0f;

    for (int kc = 0; kc < 128; kc += 32) {
        __syncthreads();
        // x tile: 128 rows x 32 k  (1024 float4 loads)
#pragma unroll
        for (int j = t; j < 1024; j += 256) {
            int r  = j >> 3;            // 0..127
            int k4 = j & 7;             // 0..7
            int row = row0 + r;
            if (row >= n) row = n - 1;
            float4 v = ((const float4*)x)[row * 32 + (kc >> 2) + k4];
            uint32_t* p = &xs[r * 36 + k4 * 4];
            p[0] = f2tf32(v.x); p[1] = f2tf32(v.y);
            p[2] = f2tf32(v.z); p[3] = f2tf32(v.w);
        }
        // W chunk: 32 k x 128 n  (1024 float4 loads)
#pragma unroll
        for (int j = t; j < 1024; j += 256) {
            int k  = j >> 5;            // 0..31
            int n4 = j & 31;            // 0..31
            float4 v = ((const float4*)W)[(kc + k) * 32 + n4];
            uint32_t* p = &ws[k * 136 + n4 * 4];
            p[0] = f2tf32(v.x); p[1] = f2tf32(v.y);
            p[2] = f2tf32(v.z); p[3] = f2tf32(v.w);
        }
        __syncthreads();

#pragma unroll
        for (int ks = 0; ks < 32; ks += 8) {
            uint32_t a[2][4];
#pragma unroll
            for (int mt = 0; mt < 2; mt++) {
                int mrow = warp_m * 32 + mt * 16 + g;
                a[mt][0] = xs[mrow * 36 + ks + c];
                a[mt][1] = xs[(mrow + 8) * 36 + ks + c];
                a[mt][2] = xs[mrow * 36 + ks + c + 4];
                a[mt][3] = xs[(mrow + 8) * 36 + ks + c + 4];
            }
            uint32_t b[8][2];
#pragma unroll
            for (int nt = 0; nt < 8; nt++) {
                int ncol = warp_n * 64 + nt * 8 + g;
                b[nt][0] = ws[(ks + c) * 136 + ncol];
                b[nt][1] = ws[(ks + c + 4) * 136 + ncol];
            }
#pragma unroll
            for (int mt = 0; mt < 2; mt++)
#pragma unroll
                for (int nt = 0; nt < 8; nt++) {
                    asm volatile(
                        "mma.sync.aligned.m16n8k8.row.col.f32.tf32.tf32.f32 "
                        "{%0,%1,%2,%3}, {%4,%5,%6,%7}, {%8,%9}, {%0,%1,%2,%3};"
                        : "+f"(acc[mt][nt][0]), "+f"(acc[mt][nt][1]),
                          "+f"(acc[mt][nt][2]), "+f"(acc[mt][nt][3])
                        : "r"(a[mt][0]), "r"(a[mt][1]), "r"(a[mt][2]), "r"(a[mt][3]),
                          "r"(b[nt][0]), "r"(b[nt][1]));
                }
        }
    }

    // epilogue: c0/c1 -> (row g,   cols 2c, 2c+1)
    //           c2/c3 -> (row g+8, cols 2c, 2c+1)
#pragma unroll
    for (int mt = 0; mt < 2; mt++) {
#pragma unroll
        for (int half = 0; half < 2; half++) {
            int row = row0 + warp_m * 32 + mt * 16 + g + half * 8;
            if (row < n) {
                float dv = g_dinv[row];
                float s  = dv * dv;
#pragma unroll
                for (int nt = 0; nt < 8; nt++) {
                    int col = warp_n * 64 + nt * 8 + c * 2;
                    float v0 = acc[mt][nt][half * 2];
                    float v1 = acc[mt][nt][half * 2 + 1];
                    ((float2*)g_xw)[(row * 128 + col) >> 1]  = make_float2(v0, v1);
                    ((float2*)g_agg)[(row * 128 + col) >> 1] = make_float2(v0 * s, v1 * s);
                }
            }
        }
    }
}

// ---------------------------------------------------------------------------
// K3: edge scatter — one warp per edge, vector RED into agg[dst]
// ---------------------------------------------------------------------------
__global__ void k_scatter(const int* __restrict__ ei, int E) {
    int gt   = blockIdx.x * blockDim.x + threadIdx.x;
    int e    = gt >> 5;
    int lane = gt & 31;
    if (e >= E) return;
    int src = __ldg(&ei[e]);
    int dst = __ldg(&ei[E + e]);
    float norm = g_dinv[src] * g_dinv[dst];
    float4 v = ((const float4*)g_xw)[src * 32 + lane];
    v.x *= norm; v.y *= norm; v.z *= norm; v.w *= norm;
    float* p = g_agg + (size_t)dst * CC + lane * 4;
    asm volatile("red.global.add.v4.f32 [%0], {%1, %2, %3, %4};"
                 :: "l"(p), "f"(v.x), "f"(v.y), "f"(v.z), "f"(v.w)
                 : "memory");
}

// ---------------------------------------------------------------------------
// K4: finalize — bias, LayerNorm(C=128), LeakyReLU, residual. One warp/node.
// ---------------------------------------------------------------------------
__global__ void k_finalize(const float* __restrict__ x,
                           const float* __restrict__ b,
                           const float* __restrict__ gamma,
                           const float* __restrict__ beta,
                           float* __restrict__ out, int n) {
    int gt   = blockIdx.x * blockDim.x + threadIdx.x;
    int node = gt >> 5;
    int lane = gt & 31;
    if (node >= n) return;

    float4 v  = ((const float4*)g_agg)[node * 32 + lane];
    float4 bv = ((const float4*)b)[lane];
    v.x += bv.x; v.y += bv.y; v.z += bv.z; v.w += bv.w;

    float sum = v.x + v.y + v.z + v.w;
#pragma unroll
    for (int off = 16; off > 0; off >>= 1)
        sum += __shfl_xor_sync(0xffffffffu, sum, off);
    float mean = sum * (1.0f / 128.0f);

    float cx = v.x - mean, cy = v.y - mean, cz = v.z - mean, cw = v.w - mean;
    float sq = cx * cx + cy * cy + cz * cz + cw * cw;
#pragma unroll
    for (int off = 16; off > 0; off >>= 1)
        sq += __shfl_xor_sync(0xffffffffu, sq, off);
    float var  = sq * (1.0f / 128.0f);
    float rstd = rsqrtf(var + 1e-5f);

    float4 g  = ((const float4*)gamma)[lane];
    float4 be = ((const float4*)beta)[lane];
    float4 xr = ((const float4*)x)[node * 32 + lane];

    float4 o;
    o.x = fmaf(cx * rstd, g.x, be.x);
    o.y = fmaf(cy * rstd, g.y, be.y);
    o.z = fmaf(cz * rstd, g.z, be.z);
    o.w = fmaf(cw * rstd, g.w, be.w);
    o.x = (o.x >= 0.0f ? o.x : 0.01f * o.x) + xr.x;
    o.y = (o.y >= 0.0f ? o.y : 0.01f * o.y) + xr.y;
    o.z = (o.z >= 0.0f ? o.z : 0.01f * o.z) + xr.z;
    o.w = (o.w >= 0.0f ? o.w : 0.01f * o.w) + xr.w;

    ((float4*)out)[node * 32 + lane] = o;
}

// ---------------------------------------------------------------------------
// Host launcher (graph-capturable: kernel launches only, default stream)
// ---------------------------------------------------------------------------
extern "C" void kernel_launch(void* const* d_in, const int* in_sizes, int n_in,
                              void* d_out, int out_size) {
    const float* x     = (const float*)d_in[0];
    const int*   ei    = (const int*)d_in[1];
    const float* W     = (const float*)d_in[2];
    const float* b     = (const float*)d_in[3];
    const float* gamma = (const float*)d_in[4];
    const float* beta  = (const float*)d_in[5];
    float* out = (float*)d_out;

    const int n = in_sizes[0] / CC;      // 50000
    const int E = in_sizes[1] / 2;       // 600000

    k_zero_deg<<<(n + 255) / 256, 256>>>(n);
    k_count<<<(E + 255) / 256, 256>>>(ei, E);
    k_dinv<<<(n + 255) / 256, 256>>>(n);
    k_gemm_tc<<<(n + 127) / 128, 256>>>(x, W, n);
    k_scatter<<<((long long)E * 32 + 255) / 256, 256>>>(ei, E);
    k_finalize<<<(n * 32 + 255) / 256, 256>>>(x, b, gamma, beta, out, n);
}

// round 16
// speedup vs baseline: 1.8955x; 1.0213x over previous
#include <cuda_runtime.h>
#include <cuda_bf16.h>
#include <cstdint>

#define NN 50000
#define EE 600000
#define CC 128

// Scratch (device globals — no runtime allocation allowed)
__device__ float        g_xw[NN * CC];
__device__ float        g_agg[NN * CC];
__device__ float        g_dinv[NN];
__device__ unsigned int g_deg[NN];

// ---------------------------------------------------------------------------
// K0: zero degree counters
// ---------------------------------------------------------------------------
__global__ void k_zero_deg(int n) {
    int i = blockIdx.x * blockDim.x + threadIdx.x;
    if (i < n) g_deg[i] = 0u;
}

// ---------------------------------------------------------------------------
// K1: degree histogram over dst
// ---------------------------------------------------------------------------
__global__ void k_count(const int* __restrict__ ei, int E) {
    int e = blockIdx.x * blockDim.x + threadIdx.x;
    if (e < E) atomicAdd(&g_deg[ei[E + e]], 1u);
}

// ---------------------------------------------------------------------------
// K1b: dinv = rsqrt(deg + 1)
// ---------------------------------------------------------------------------
__global__ void k_dinv(int n) {
    int i = blockIdx.x * blockDim.x + threadIdx.x;
    if (i < n) g_dinv[i] = rsqrtf((float)g_deg[i] + 1.0f);
}

// ---------------------------------------------------------------------------
// K2: xw = x @ W via tf32 mma.sync.m16n8k8, cp.async 2-stage pipeline.
//     Block tile 128x128, 8 warps 4(m) x 2(n). K chunked by 16 (8 chunks)
//     so the double buffer fits the 48KB static smem limit:
//       xs[2][128*20] + ws[2][16*136] = 37,888 bytes.
//     Raw f32 bits feed the tf32 MMA (HW truncation; rel_err budget ok).
//     Epilogue writes g_xw and g_agg = xw * dinv^2 (self-loop init).
//
//     Conflict-free fragment banks:
//       xs k-stride 20: bank = (20g + c) mod 32 -> {0,20,8,28,16,4,24,12}+c, all 32 distinct
//       ws n-stride 136: bank = (8c + g) mod 32 -> all 32 distinct
// ---------------------------------------------------------------------------
#define XS_WORDS (128 * 20)
#define WS_WORDS (16 * 136)

__device__ __forceinline__ void cp16(uint32_t smem_addr, const void* gptr) {
    asm volatile("cp.async.cg.shared.global [%0], [%1], 16;"
                 :: "r"(smem_addr), "l"(gptr));
}

__global__ __launch_bounds__(256) void k_gemm_tc(const float* __restrict__ x,
                                                 const float* __restrict__ W,
                                                 int n) {
    __shared__ uint32_t xs[2][XS_WORDS];   // [stage][m][k], k-stride 20
    __shared__ uint32_t ws[2][WS_WORDS];   // [stage][k][n], n-stride 136

    const int t      = threadIdx.x;
    const int lane   = t & 31;
    const int warp   = t >> 5;
    const int g      = lane >> 2;
    const int c      = lane & 3;
    const int warp_m = warp >> 1;       // 0..3
    const int warp_n = warp & 1;        // 0..1
    const int row0   = blockIdx.x * 128;

    uint32_t xs_base[2], ws_base[2];
    {
        uint32_t a0, a1;
        asm("{ .reg .u64 tt; cvta.to.shared.u64 tt, %2; cvt.u32.u64 %0, tt;\n\t"
            "  .reg .u64 uu; cvta.to.shared.u64 uu, %3; cvt.u32.u64 %1, uu; }"
            : "=r"(a0), "=r"(a1) : "l"(&xs[0][0]), "l"(&ws[0][0]));
        xs_base[0] = a0; xs_base[1] = a0 + XS_WORDS * 4;
        ws_base[0] = a1; ws_base[1] = a1 + WS_WORDS * 4;
    }

    // issue all cp.asyncs for K-chunk kc (16 wide) into stage s
    auto load_stage = [&](int kc, int s) {
        // x tile: 128 rows x 16 k -> 512 16B copies
#pragma unroll
        for (int j = t; j < 512; j += 256) {
            int r  = j >> 2;            // 0..127
            int k4 = j & 3;             // 0..3
            int row = row0 + r;
            if (row >= n) row = n - 1;
            cp16(xs_base[s] + (r * 20 + k4 * 4) * 4,
                 &((const float4*)x)[row * 32 + (kc >> 2) + k4]);
        }
        // W chunk: 16 k x 128 n -> 512 16B copies
#pragma unroll
        for (int j = t; j < 512; j += 256) {
            int k  = j >> 5;            // 0..15
            int n4 = j & 31;            // 0..31
            cp16(ws_base[s] + (k * 136 + n4 * 4) * 4,
                 &((const float4*)W)[(kc + k) * 32 + n4]);
        }
        asm volatile("cp.async.commit_group;" ::: "memory");
    };

    float acc[2][8][4];
#pragma unroll
    for (int mt = 0; mt < 2; mt++)
#pragma unroll
        for (int nt = 0; nt < 8; nt++)
#pragma unroll
            for (int q = 0; q < 4; q++) acc[mt][nt][q] = 0.0f;

    load_stage(0, 0);

#pragma unroll
    for (int kci = 0; kci < 8; kci++) {
        const int s = kci & 1;
        if (kci < 7) {
            load_stage((kci + 1) * 16, s ^ 1);
            asm volatile("cp.async.wait_group 1;" ::: "memory");
        } else {
            asm volatile("cp.async.wait_group 0;" ::: "memory");
        }
        __syncthreads();

        const uint32_t* xsp = &xs[s][0];
        const uint32_t* wsp = &ws[s][0];
#pragma unroll
        for (int ks = 0; ks < 16; ks += 8) {
            uint32_t a[2][4];
#pragma unroll
            for (int mt = 0; mt < 2; mt++) {
                int mrow = warp_m * 32 + mt * 16 + g;
                a[mt][0] = xsp[mrow * 20 + ks + c];
                a[mt][1] = xsp[(mrow + 8) * 20 + ks + c];
                a[mt][2] = xsp[mrow * 20 + ks + c + 4];
                a[mt][3] = xsp[(mrow + 8) * 20 + ks + c + 4];
            }
            uint32_t b[8][2];
#pragma unroll
            for (int nt = 0; nt < 8; nt++) {
                int ncol = warp_n * 64 + nt * 8 + g;
                b[nt][0] = wsp[(ks + c) * 136 + ncol];
                b[nt][1] = wsp[(ks + c + 4) * 136 + ncol];
            }
#pragma unroll
            for (int mt = 0; mt < 2; mt++)
#pragma unroll
                for (int nt = 0; nt < 8; nt++) {
                    asm volatile(
                        "mma.sync.aligned.m16n8k8.row.col.f32.tf32.tf32.f32 "
                        "{%0,%1,%2,%3}, {%4,%5,%6,%7}, {%8,%9}, {%0,%1,%2,%3};"
                        : "+f"(acc[mt][nt][0]), "+f"(acc[mt][nt][1]),
                          "+f"(acc[mt][nt][2]), "+f"(acc[mt][nt][3])
                        : "r"(a[mt][0]), "r"(a[mt][1]), "r"(a[mt][2]), "r"(a[mt][3]),
                          "r"(b[nt][0]), "r"(b[nt][1]));
                }
        }
        __syncthreads();
    }

    // epilogue: c0/c1 -> (row g,   cols 2c, 2c+1); c2/c3 -> (row g+8, ...)
#pragma unroll
    for (int mt = 0; mt < 2; mt++) {
#pragma unroll
        for (int half = 0; half < 2; half++) {
            int row = row0 + warp_m * 32 + mt * 16 + g + half * 8;
            if (row < n) {
                float dv = g_dinv[row];
                float s2 = dv * dv;
#pragma unroll
                for (int nt = 0; nt < 8; nt++) {
                    int col = warp_n * 64 + nt * 8 + c * 2;
                    float v0 = acc[mt][nt][half * 2];
                    float v1 = acc[mt][nt][half * 2 + 1];
                    ((float2*)g_xw)[(row * 128 + col) >> 1]  = make_float2(v0, v1);
                    ((float2*)g_agg)[(row * 128 + col) >> 1] = make_float2(v0 * s2, v1 * s2);
                }
            }
        }
    }
}

// ---------------------------------------------------------------------------
// K3: edge scatter — one warp per edge, vector RED into agg[dst]
// ---------------------------------------------------------------------------
__global__ void k_scatter(const int* __restrict__ ei, int E) {
    int gt   = blockIdx.x * blockDim.x + threadIdx.x;
    int e    = gt >> 5;
    int lane = gt & 31;
    if (e >= E) return;
    int src = __ldg(&ei[e]);
    int dst = __ldg(&ei[E + e]);
    float norm = g_dinv[src] * g_dinv[dst];
    float4 v = ((const float4*)g_xw)[src * 32 + lane];
    v.x *= norm; v.y *= norm; v.z *= norm; v.w *= norm;
    float* p = g_agg + (size_t)dst * CC + lane * 4;
    asm volatile("red.global.add.v4.f32 [%0], {%1, %2, %3, %4};"
                 :: "l"(p), "f"(v.x), "f"(v.y), "f"(v.z), "f"(v.w)
                 : "memory");
}

// ---------------------------------------------------------------------------
// K4: finalize — bias, LayerNorm(C=128), LeakyReLU, residual. One warp/node.
// ---------------------------------------------------------------------------
__global__ void k_finalize(const float* __restrict__ x,
                           const float* __restrict__ b,
                           const float* __restrict__ gamma,
                           const float* __restrict__ beta,
                           float* __restrict__ out, int n) {
    int gt   = blockIdx.x * blockDim.x + threadIdx.x;
    int node = gt >> 5;
    int lane = gt & 31;
    if (node >= n) return;

    float4 v  = ((const float4*)g_agg)[node * 32 + lane];
    float4 bv = ((const float4*)b)[lane];
    v.x += bv.x; v.y += bv.y; v.z += bv.z; v.w += bv.w;

    float sum = v.x + v.y + v.z + v.w;
#pragma unroll
    for (int off = 16; off > 0; off >>= 1)
        sum += __shfl_xor_sync(0xffffffffu, sum, off);
    float mean = sum * (1.0f / 128.0f);

    float cx = v.x - mean, cy = v.y - mean, cz = v.z - mean, cw = v.w - mean;
    float sq = cx * cx + cy * cy + cz * cz + cw * cw;
#pragma unroll
    for (int off = 16; off > 0; off >>= 1)
        sq += __shfl_xor_sync(0xffffffffu, sq, off);
    float var  = sq * (1.0f / 128.0f);
    float rstd = rsqrtf(var + 1e-5f);

    float4 g  = ((const float4*)gamma)[lane];
    float4 be = ((const float4*)beta)[lane];
    float4 xr = ((const float4*)x)[node * 32 + lane];

    float4 o;
    o.x = fmaf(cx * rstd, g.x, be.x);
    o.y = fmaf(cy * rstd, g.y, be.y);
    o.z = fmaf(cz * rstd, g.z, be.z);
    o.w = fmaf(cw * rstd, g.w, be.w);
    o.x = (o.x >= 0.0f ? o.x : 0.01f * o.x) + xr.x;
    o.y = (o.y >= 0.0f ? o.y : 0.01f * o.y) + xr.y;
    o.z = (o.z >= 0.0f ? o.z : 0.01f * o.z) + xr.z;
    o.w = (o.w >= 0.0f ? o.w : 0.01f * o.w) + xr.w;

    ((float4*)out)[node * 32 + lane] = o;
}

// ---------------------------------------------------------------------------
// Host launcher (graph-capturable: kernel launches only, default stream)
// ---------------------------------------------------------------------------
extern "C" void kernel_launch(void* const* d_in, const int* in_sizes, int n_in,
                              void* d_out, int out_size) {
    const float* x     = (const float*)d_in[0];
    const int*   ei    = (const int*)d_in[1];
    const float* W     = (const float*)d_in[2];
    const float* b     = (const float*)d_in[3];
    const float* gamma = (const float*)d_in[4];
    const float* beta  = (const float*)d_in[5];
    float* out = (float*)d_out;

    const int n = in_sizes[0] / CC;      // 50000
    const int E = in_sizes[1] / 2;       // 600000

    k_zero_deg<<<(n + 255) / 256, 256>>>(n);
    k_count<<<(E + 255) / 256, 256>>>(ei, E);
    k_dinv<<<(n + 255) / 256, 256>>>(n);
    k_gemm_tc<<<(n + 127) / 128, 256>>>(x, W, n);
    k_scatter<<<((long long)E * 32 + 255) / 256, 256>>>(ei, E);
    k_finalize<<<(n * 32 + 255) / 256, 256>>>(x, b, gamma, beta, out, n);
}